// round 14
// baseline (speedup 1.0000x reference)
#include <cuda_runtime.h>
#include <cuda_bf16.h>
#include <math.h>
#include <stdint.h>

// ---------------------------------------------------------------------------
// Problem constants
// ---------------------------------------------------------------------------
#define S_LEN 1024
#define BATCH 2
#define NTOK  2048          // B*S
#define EDIM  512
#define HDIM  1024
#define MDIM  256
#define VDIM  32000

// ---------------------------------------------------------------------------
// Scratch (device globals)
// ---------------------------------------------------------------------------
__device__ float g_xp[NTOK * 3 * HDIM];
__device__ float g_states[NTOK * HDIM];
__device__ float g_h[2 * BATCH * HDIM];
__device__ float g_base[NTOK * EDIM];
__device__ float g_gate[NTOK];
__device__ float g_q[NTOK * MDIM];
__device__ float g_k[NTOK * MDIM];
__device__ unsigned g_bar_cnt;

// Split (hi/lo bf16) planes for tensor-core GEMMs
__device__ __nv_bfloat16 s_embW_h[VDIM * EDIM],     s_embW_l[VDIM * EDIM];
__device__ __nv_bfloat16 s_emb_h [NTOK * EDIM],     s_emb_l [NTOK * EDIM];
__device__ __nv_bfloat16 s_wih_h [3 * HDIM * EDIM], s_wih_l [3 * HDIM * EDIM];
__device__ __nv_bfloat16 s_st_h  [NTOK * HDIM],     s_st_l  [NTOK * HDIM];
__device__ __nv_bfloat16 s_W1_h  [4 * EDIM * HDIM], s_W1_l  [4 * EDIM * HDIM];
__device__ __nv_bfloat16 s_hf_h  [NTOK * 4 * EDIM], s_hf_l  [NTOK * 4 * EDIM];
__device__ __nv_bfloat16 s_W2_h  [EDIM * 4 * EDIM], s_W2_l  [EDIM * 4 * EDIM];
__device__ __nv_bfloat16 s_base_h[NTOK * EDIM],     s_base_l[NTOK * EDIM];
__device__ __nv_bfloat16 s_comb_h[NTOK * EDIM],     s_comb_l[NTOK * EDIM];
__device__ __nv_bfloat16 s_Wq_h  [MDIM * HDIM],     s_Wq_l  [MDIM * HDIM];
__device__ __nv_bfloat16 s_Wk_h  [MDIM * HDIM],     s_Wk_l  [MDIM * HDIM];
__device__ __nv_bfloat16 s_Wr_h  [EDIM * EDIM],     s_Wr_l  [EDIM * EDIM];

// ---------------------------------------------------------------------------
// Init: zero recurrent state + reset grid barrier
// ---------------------------------------------------------------------------
__global__ void init_kernel() {
    int i = blockIdx.x * blockDim.x + threadIdx.x;
    if (i < 2 * BATCH * HDIM) g_h[i] = 0.f;
    if (i == 0) g_bar_cnt = 0u;
}

// ---------------------------------------------------------------------------
// Split helpers
// ---------------------------------------------------------------------------
__device__ __forceinline__ void split1(float x, __nv_bfloat16& h, __nv_bfloat16& l) {
    h = __float2bfloat16(x);
    l = __float2bfloat16(x - __bfloat162float(h));
}

// Fused embedding gather + hi/lo split
__global__ void embed_split_kernel(const int* __restrict__ ids,
                                   const float* __restrict__ embW) {
    int t = blockIdx.x;
    int c = threadIdx.x;                   // 128 threads, one float4 each
    int id = ids[t];
    float4 v = ((const float4*)embW)[(size_t)id * (EDIM / 4) + c];
    __nv_bfloat16 h0, h1, h2, h3, l0, l1, l2, l3;
    split1(v.x, h0, l0); split1(v.y, h1, l1);
    split1(v.z, h2, l2); split1(v.w, h3, l3);
    size_t o = (size_t)t * (EDIM / 2) + 2 * c;   // bf16x2 units
    ((__nv_bfloat162*)s_emb_h)[o]     = __nv_bfloat162(h0, h1);
    ((__nv_bfloat162*)s_emb_h)[o + 1] = __nv_bfloat162(h2, h3);
    ((__nv_bfloat162*)s_emb_l)[o]     = __nv_bfloat162(l0, l1);
    ((__nv_bfloat162*)s_emb_l)[o + 1] = __nv_bfloat162(l2, l3);
}

// Generic fp32 -> (hi, lo) bf16 split.  x = hi + lo + O(2^-18 x)
__global__ void __launch_bounds__(256) split_kernel(
    const float* __restrict__ src,
    __nv_bfloat16* __restrict__ hi, __nv_bfloat16* __restrict__ lo, int n4)
{
    int i = blockIdx.x * blockDim.x + threadIdx.x;
    if (i >= n4) return;
    float4 v = ((const float4*)src)[i];
    __nv_bfloat16 h0, h1, h2, h3, l0, l1, l2, l3;
    split1(v.x, h0, l0); split1(v.y, h1, l1);
    split1(v.z, h2, l2); split1(v.w, h3, l3);
    ((__nv_bfloat162*)hi)[2 * i]     = __nv_bfloat162(h0, h1);
    ((__nv_bfloat162*)hi)[2 * i + 1] = __nv_bfloat162(h2, h3);
    ((__nv_bfloat162*)lo)[2 * i]     = __nv_bfloat162(l0, l1);
    ((__nv_bfloat162*)lo)[2 * i + 1] = __nv_bfloat162(l2, l3);
}

// ---------------------------------------------------------------------------
// Tensor-core GEMM (error-compensated bf16 split):
//   C[m][n] = f(sum_k A[m][k]*B[n][k] + bias[n])
// computed as A_hi*B_hi + A_lo*B_hi + A_hi*B_lo  (lo*lo dropped, ~2^-18)
// Block 128x128, 8 warps (4m x 2n), warp tile 32x64, K-tile 32.
// cp.async double-buffered SMEM; __launch_bounds__(256,2) for 2 CTAs/SM.
// Grid: x = M-tile (fastest) so a wave shares B tiles through L2.
// epi flags: 1=relu(x)^2   2=auxb+auxg*relu(x)   4=write fp32 C
//            8=write split planes (Chi/Clo)
// ---------------------------------------------------------------------------
#define EPI_RELU2 1
#define EPI_GATE  2
#define EPI_F32   4
#define EPI_SPLIT 8

__device__ __forceinline__ void ldsm4(uint32_t& r0, uint32_t& r1,
                                      uint32_t& r2, uint32_t& r3, uint32_t a) {
    asm volatile("ldmatrix.sync.aligned.m8n8.x4.shared.b16 {%0,%1,%2,%3}, [%4];"
                 : "=r"(r0), "=r"(r1), "=r"(r2), "=r"(r3) : "r"(a));
}
__device__ __forceinline__ void mma16816(float* d, const uint32_t* a,
                                         const uint32_t* b) {
    asm volatile(
        "mma.sync.aligned.m16n8k16.row.col.f32.bf16.bf16.f32 "
        "{%0,%1,%2,%3}, {%4,%5,%6,%7}, {%8,%9}, {%0,%1,%2,%3};"
        : "+f"(d[0]), "+f"(d[1]), "+f"(d[2]), "+f"(d[3])
        : "r"(a[0]), "r"(a[1]), "r"(a[2]), "r"(a[3]), "r"(b[0]), "r"(b[1]));
}
__device__ __forceinline__ void cpasync16(uint32_t saddr, const void* gaddr) {
    asm volatile("cp.async.cg.shared.global [%0], [%1], 16;"
                 :: "r"(saddr), "l"(gaddr));
}

#define HMMA_SMEM (2 * 4 * 128 * 40 * 2)   // 81920 bytes

__global__ void __launch_bounds__(256, 2) hmma_kernel(
    const __nv_bfloat16* __restrict__ Ahi, const __nv_bfloat16* __restrict__ Alo,
    const __nv_bfloat16* __restrict__ Bhi, const __nv_bfloat16* __restrict__ Blo,
    const float* __restrict__ bias, float* __restrict__ C,
    int M, int N, int K, int epi,
    const float* __restrict__ auxb, const float* __restrict__ auxg,
    __nv_bfloat16* __restrict__ Chi, __nv_bfloat16* __restrict__ Clo)
{
    extern __shared__ __nv_bfloat16 dynsm[];
    const uint32_t smem0 = (uint32_t)__cvta_generic_to_shared(dynsm);
    const int tid = threadIdx.x;
    const int lane = tid & 31, wid = tid >> 5;
    const int wm = wid & 3, wn = wid >> 2;
    const int row0 = blockIdx.x * 128, col0 = blockIdx.y * 128;

    float acc[2][8][4];
#pragma unroll
    for (int mi = 0; mi < 2; ++mi)
#pragma unroll
        for (int ni = 0; ni < 8; ++ni)
#pragma unroll
            for (int u = 0; u < 4; ++u) acc[mi][ni][u] = 0.f;

    const int rA = tid >> 2;            // 0..63
    const int ko = (tid & 3) * 8;       // 0,8,16,24

    const int rlA = (lane & 7) + ((lane >> 3) & 1) * 8;
    const int clA = (lane >> 4) * 8;
    const uint32_t aOff = (uint32_t)(((wm * 32 + rlA) * 40 + clA) * 2);
    const int rlB = (lane & 7) + (lane >= 16 ? 8 : 0);
    const int clB = ((lane >> 3) & 1) * 8;
    const uint32_t bOff = (uint32_t)(((wn * 64 + rlB) * 40 + clB) * 2);

    const int nkt = K >> 5;

    auto prefetch = [&](int kt) {
        const int k0 = kt << 5;
        const uint32_t sb = smem0 + (uint32_t)(kt & 1) * 40960u;
        const size_t ga0 = (size_t)(row0 + rA)      * K + k0 + ko;
        const size_t ga1 = (size_t)(row0 + rA + 64) * K + k0 + ko;
        const size_t gb0 = (size_t)(col0 + rA)      * K + k0 + ko;
        const size_t gb1 = (size_t)(col0 + rA + 64) * K + k0 + ko;
        const uint32_t s0 = sb + (uint32_t)((rA * 40 + ko) * 2);
        const uint32_t s1 = sb + (uint32_t)(((rA + 64) * 40 + ko) * 2);
        cpasync16(s0,          Ahi + ga0); cpasync16(s1,          Ahi + ga1);
        cpasync16(s0 + 10240u, Alo + ga0); cpasync16(s1 + 10240u, Alo + ga1);
        cpasync16(s0 + 20480u, Bhi + gb0); cpasync16(s1 + 20480u, Bhi + gb1);
        cpasync16(s0 + 30720u, Blo + gb0); cpasync16(s1 + 30720u, Blo + gb1);
    };

    prefetch(0);
    asm volatile("cp.async.commit_group;");

    for (int kt = 0; kt < nkt; ++kt) {
        if (kt + 1 < nkt) {
            prefetch(kt + 1);
            asm volatile("cp.async.commit_group;");
            asm volatile("cp.async.wait_group 1;");
        } else {
            asm volatile("cp.async.wait_group 0;");
        }
        __syncthreads();
        const uint32_t base = smem0 + (uint32_t)(kt & 1) * 40960u;
#pragma unroll
        for (int ks = 0; ks < 2; ++ks) {
            uint32_t ah[2][4], al[2][4];
#pragma unroll
            for (int mi = 0; mi < 2; ++mi) {
                uint32_t ka = base + aOff + (uint32_t)(mi * 1280 + ks * 32);
                ldsm4(ah[mi][0], ah[mi][1], ah[mi][2], ah[mi][3], ka);
                ldsm4(al[mi][0], al[mi][1], al[mi][2], al[mi][3], ka + 10240u);
            }
#pragma unroll
            for (int np = 0; np < 4; ++np) {
                uint32_t kb = base + 20480u + bOff +
                              (uint32_t)(np * 1280 + ks * 32);
                uint32_t bh[4], bl[4];
                ldsm4(bh[0], bh[1], bh[2], bh[3], kb);
                ldsm4(bl[0], bl[1], bl[2], bl[3], kb + 10240u);
#pragma unroll
                for (int mi = 0; mi < 2; ++mi) {
                    mma16816(acc[mi][2 * np],     ah[mi], bh);
                    mma16816(acc[mi][2 * np],     al[mi], bh);
                    mma16816(acc[mi][2 * np],     ah[mi], bl);
                    mma16816(acc[mi][2 * np + 1], ah[mi], bh + 2);
                    mma16816(acc[mi][2 * np + 1], al[mi], bh + 2);
                    mma16816(acc[mi][2 * np + 1], ah[mi], bl + 2);
                }
            }
        }
        __syncthreads();
    }

    // Epilogue
    const int g = lane >> 2, tg = lane & 3;
#pragma unroll
    for (int mi = 0; mi < 2; ++mi) {
        const int r = row0 + wm * 32 + mi * 16 + g;
#pragma unroll
        for (int ni = 0; ni < 8; ++ni) {
            const int c = col0 + wn * 64 + ni * 8 + tg * 2;
            const float b0 = bias[c], b1 = bias[c + 1];
            float v[2][2] = {{acc[mi][ni][0] + b0, acc[mi][ni][1] + b1},
                             {acc[mi][ni][2] + b0, acc[mi][ni][3] + b1}};
#pragma unroll
            for (int rr = 0; rr < 2; ++rr) {
                const int row = r + rr * 8;
                if (epi & EPI_RELU2) {
#pragma unroll
                    for (int u = 0; u < 2; ++u) {
                        float x = fmaxf(v[rr][u], 0.f); v[rr][u] = x * x;
                    }
                } else if (epi & EPI_GATE) {
                    float gg = auxg[row];
#pragma unroll
                    for (int u = 0; u < 2; ++u)
                        v[rr][u] = auxb[(size_t)row * N + c + u] +
                                   gg * fmaxf(v[rr][u], 0.f);
                }
                if (epi & EPI_F32)
                    *(float2*)(C + (size_t)row * N + c) =
                        make_float2(v[rr][0], v[rr][1]);
                if (epi & EPI_SPLIT) {
                    __nv_bfloat16 h0, h1, l0, l1;
                    split1(v[rr][0], h0, l0);
                    split1(v[rr][1], h1, l1);
                    *(__nv_bfloat162*)(Chi + (size_t)row * N + c) =
                        __nv_bfloat162(h0, h1);
                    *(__nv_bfloat162*)(Clo + (size_t)row * N + c) =
                        __nv_bfloat162(l0, l1);
                }
            }
        }
    }
}

// ---------------------------------------------------------------------------
// GRU: persistent kernel (R13 version) + in-place hi/lo split of states.
// ---------------------------------------------------------------------------
#define GRU_CTAS    128
#define GRU_THREADS 256
#define GRU_SMEM    ((24 * HDIM + BATCH * HDIM) * 4)

__device__ __forceinline__ float warp_sum(float v) {
#pragma unroll
    for (int o = 16; o; o >>= 1) v += __shfl_xor_sync(0xffffffffu, v, o);
    return v;
}

__global__ void __launch_bounds__(GRU_THREADS, 1) gru_kernel(
    const float* __restrict__ xp, const float* __restrict__ w_hh,
    const float* __restrict__ b_hh)
{
    extern __shared__ float sm[];
    float* wsm = sm;                       // [24][HDIM], row = gate*8 + jl
    float* hsm = sm + 24 * HDIM;           // [BATCH][HDIM]
    const int tid = threadIdx.x;
    const int w = tid >> 5, lane = tid & 31;
    const int j0 = blockIdx.x * 8;

    for (int v = tid; v < 24 * (HDIM / 4); v += GRU_THREADS) {
        int rowl = v / (HDIM / 4);
        int c4 = v % (HDIM / 4);
        int g = rowl >> 3, jl = rowl & 7;
        ((float4*)wsm)[(size_t)rowl * (HDIM / 4) + c4] =
            ((const float4*)w_hh)[(size_t)(g * HDIM + j0 + jl) * (HDIM / 4) + c4];
    }
    const int j = j0 + w;
    const float bhr = b_hh[j];
    const float bhz = b_hh[HDIM + j];
    const float bhn = b_hh[2 * HDIM + j];
    __syncthreads();

    float xv0 = 0.f, xv1 = 0.f, xv2 = 0.f;
    if (lane < 2) {
        const float* xpt = xp + ((size_t)lane * S_LEN) * (3 * HDIM);
        xv0 = xpt[j]; xv1 = xpt[HDIM + j]; xv2 = xpt[2 * HDIM + j];
    }

    for (int s = 0; s < S_LEN; ++s) {
        const float* h_in = g_h + (s & 1) * (BATCH * HDIM);
        float* h_out      = g_h + ((s + 1) & 1) * (BATCH * HDIM);

        for (int v = tid; v < (BATCH * HDIM) / 4; v += GRU_THREADS)
            ((float4*)hsm)[v] = __ldcg(((const float4*)h_in) + v);
        __syncthreads();

        float xn0 = 0.f, xn1 = 0.f, xn2 = 0.f;
        if (lane < 2 && s + 1 < S_LEN) {
            const float* xpt = xp + ((size_t)lane * S_LEN + s + 1) * (3 * HDIM);
            xn0 = __ldg(xpt + j);
            xn1 = __ldg(xpt + HDIM + j);
            xn2 = __ldg(xpt + 2 * HDIM + j);
        }

        float4 H0[8], H1[8];
#pragma unroll
        for (int c = 0; c < 8; ++c) {
            H0[c] = ((const float4*)hsm)[lane + 32 * c];
            H1[c] = ((const float4*)(hsm + HDIM))[lane + 32 * c];
        }
        float acc[3][2];
#pragma unroll
        for (int g = 0; g < 3; ++g) {
            const float4* wp = (const float4*)(wsm + (size_t)(g * 8 + w) * HDIM);
            float s0a = 0.f, s0b = 0.f, s1a = 0.f, s1b = 0.f;
#pragma unroll
            for (int c = 0; c < 8; ++c) {
                float4 wv = wp[lane + 32 * c];
                s0a = fmaf(wv.x, H0[c].x, s0a); s0b = fmaf(wv.y, H0[c].y, s0b);
                s0a = fmaf(wv.z, H0[c].z, s0a); s0b = fmaf(wv.w, H0[c].w, s0b);
                s1a = fmaf(wv.x, H1[c].x, s1a); s1b = fmaf(wv.y, H1[c].y, s1b);
                s1a = fmaf(wv.z, H1[c].z, s1a); s1b = fmaf(wv.w, H1[c].w, s1b);
            }
            acc[g][0] = warp_sum(s0a + s0b);   // result in ALL lanes
            acc[g][1] = warp_sum(s1a + s1b);
        }

        if (lane < 2) {
            const int b = lane;
            size_t t = (size_t)b * S_LEN + s;
            float r = 1.f / (1.f + __expf(-(xv0 + acc[0][b] + bhr)));
            float z = 1.f / (1.f + __expf(-(xv1 + acc[1][b] + bhz)));
            float n = tanhf(xv2 + r * (acc[2][b] + bhn));
            float hp = hsm[b * HDIM + j];
            float hn2 = (1.f - z) * n + z * hp;
            g_states[t * HDIM + j] = hn2;
            __nv_bfloat16 sh, sl;
            split1(hn2, sh, sl);
            s_st_h[t * HDIM + j] = sh;
            s_st_l[t * HDIM + j] = sl;
            __stcg(h_out + b * HDIM + j, hn2);
        }
        xv0 = xn0; xv1 = xn1; xv2 = xn2;
        __syncthreads();

        // --- grid barrier: monotonic counter, direct poll ---
        if (tid == 0) {
            __threadfence();
            atomicAdd(&g_bar_cnt, 1u);
            const unsigned target = (unsigned)GRU_CTAS * (unsigned)(s + 1);
            while (*((volatile unsigned*)&g_bar_cnt) < target) { }
            __threadfence();
        }
        __syncthreads();
    }
}

// ---------------------------------------------------------------------------
// gate[t] = sigmoid(states[t] . Wg + bg)
// ---------------------------------------------------------------------------
__global__ void gate_kernel(const float* __restrict__ Wg,
                            const float* __restrict__ bg) {
    int t = blockIdx.x;
    int tid = threadIdx.x;
    const float4* sp = (const float4*)(g_states + (size_t)t * HDIM);
    const float4* wp = (const float4*)Wg;
    float s = 0.f;
    for (int c = tid; c < HDIM / 4; c += 128) {
        float4 a = sp[c], ww = wp[c];
        s += a.x * ww.x + a.y * ww.y + a.z * ww.z + a.w * ww.w;
    }
    __shared__ float red[128];
    red[tid] = s; __syncthreads();
    for (int k = 64; k; k >>= 1) {
        if (tid < k) red[tid] += red[tid + k];
        __syncthreads();
    }
    if (tid == 0) g_gate[t] = 1.f / (1.f + expf(-(red[0] + bg[0])));
}

// ---------------------------------------------------------------------------
// Fused attention softmax + scatter-add into logits
// ---------------------------------------------------------------------------
__global__ void __launch_bounds__(256) attn_scatter_kernel(
    const int* __restrict__ ids, const float* __restrict__ mscale,
    float* __restrict__ out)
{
    int bq = blockIdx.x;
    int b = bq >> 10, qpos = bq & 1023;
    if (qpos == 0) return;
    int tid = threadIdx.x;

    __shared__ float qv[MDIM];
    __shared__ float red[256];
    if (tid < MDIM) qv[tid] = g_q[(size_t)bq * MDIM + tid];
    __syncthreads();

    const int nk = qpos;
    float sc[4];
    int cnt = 0;
    float mx = -1e30f;
    for (int kp = tid; kp < nk; kp += 256) {
        const float4* kr = (const float4*)(g_k + (size_t)(b * S_LEN + kp) * MDIM);
        float d = 0.f;
#pragma unroll 16
        for (int c = 0; c < MDIM / 4; ++c) {
            float4 kv = kr[c];
            float4 qq = ((const float4*)qv)[c];
            d += kv.x * qq.x + kv.y * qq.y + kv.z * qq.z + kv.w * qq.w;
        }
        d *= 0.0625f;
        sc[cnt++] = d;
        mx = fmaxf(mx, d);
    }
    red[tid] = mx; __syncthreads();
    for (int k = 128; k; k >>= 1) {
        if (tid < k) red[tid] = fmaxf(red[tid], red[tid + k]);
        __syncthreads();
    }
    mx = red[0]; __syncthreads();

    float sum = 0.f;
    for (int i = 0; i < cnt; ++i) { sc[i] = expf(sc[i] - mx); sum += sc[i]; }
    red[tid] = sum; __syncthreads();
    for (int k = 128; k; k >>= 1) {
        if (tid < k) red[tid] += red[tid + k];
        __syncthreads();
    }
    sum = red[0];

    float coef = g_gate[bq] * mscale[0] / sum;
    int i2 = 0;
    for (int kp = tid; kp < nk; kp += 256) {
        int vid = ids[b * S_LEN + kp];
        atomicAdd(out + (size_t)bq * VDIM + vid, sc[i2++] * coef);
    }
}

// ---------------------------------------------------------------------------
// Host launcher
// ---------------------------------------------------------------------------
extern "C" void kernel_launch(void* const* d_in, const int* in_sizes, int n_in,
                              void* d_out, int out_size) {
    (void)in_sizes; (void)n_in; (void)out_size;
    const int*   ids    = (const int*)d_in[0];
    const float* embW   = (const float*)d_in[1];
    const float* w_ih   = (const float*)d_in[2];
    const float* w_hh   = (const float*)d_in[3];
    const float* b_ih   = (const float*)d_in[4];
    const float* b_hh   = (const float*)d_in[5];
    const float* Wq     = (const float*)d_in[6];
    const float* bq     = (const float*)d_in[7];
    const float* Wk     = (const float*)d_in[8];
    const float* bk     = (const float*)d_in[9];
    const float* Wg     = (const float*)d_in[10];
    const float* bg     = (const float*)d_in[11];
    const float* W1     = (const float*)d_in[12];
    const float* b1     = (const float*)d_in[13];
    const float* W2     = (const float*)d_in[14];
    const float* b2     = (const float*)d_in[15];
    const float* Wr     = (const float*)d_in[16];
    const float* br     = (const float*)d_in[17];
    const float* mscale = (const float*)d_in[18];
    const float* obias  = (const float*)d_in[19];
    float* out = (float*)d_out;

    float *p_xp, *p_states, *p_base, *p_gate, *p_q, *p_k;
    cudaGetSymbolAddress((void**)&p_xp,     g_xp);
    cudaGetSymbolAddress((void**)&p_states, g_states);
    cudaGetSymbolAddress((void**)&p_base,   g_base);
    cudaGetSymbolAddress((void**)&p_gate,   g_gate);
    cudaGetSymbolAddress((void**)&p_q,      g_q);
    cudaGetSymbolAddress((void**)&p_k,      g_k);

    __nv_bfloat16 *q_embW_h, *q_embW_l, *q_emb_h, *q_emb_l, *q_wih_h, *q_wih_l,
                  *q_st_h, *q_st_l, *q_W1_h, *q_W1_l, *q_hf_h, *q_hf_l,
                  *q_W2_h, *q_W2_l, *q_base_h, *q_base_l, *q_comb_h, *q_comb_l,
                  *q_Wq_h, *q_Wq_l, *q_Wk_h, *q_Wk_l, *q_Wr_h, *q_Wr_l;
    cudaGetSymbolAddress((void**)&q_embW_h, s_embW_h);
    cudaGetSymbolAddress((void**)&q_embW_l, s_embW_l);
    cudaGetSymbolAddress((void**)&q_emb_h,  s_emb_h);
    cudaGetSymbolAddress((void**)&q_emb_l,  s_emb_l);
    cudaGetSymbolAddress((void**)&q_wih_h,  s_wih_h);
    cudaGetSymbolAddress((void**)&q_wih_l,  s_wih_l);
    cudaGetSymbolAddress((void**)&q_st_h,   s_st_h);
    cudaGetSymbolAddress((void**)&q_st_l,   s_st_l);
    cudaGetSymbolAddress((void**)&q_W1_h,   s_W1_h);
    cudaGetSymbolAddress((void**)&q_W1_l,   s_W1_l);
    cudaGetSymbolAddress((void**)&q_hf_h,   s_hf_h);
    cudaGetSymbolAddress((void**)&q_hf_l,   s_hf_l);
    cudaGetSymbolAddress((void**)&q_W2_h,   s_W2_h);
    cudaGetSymbolAddress((void**)&q_W2_l,   s_W2_l);
    cudaGetSymbolAddress((void**)&q_base_h, s_base_h);
    cudaGetSymbolAddress((void**)&q_base_l, s_base_l);
    cudaGetSymbolAddress((void**)&q_comb_h, s_comb_h);
    cudaGetSymbolAddress((void**)&q_comb_l, s_comb_l);
    cudaGetSymbolAddress((void**)&q_Wq_h,   s_Wq_h);
    cudaGetSymbolAddress((void**)&q_Wq_l,   s_Wq_l);
    cudaGetSymbolAddress((void**)&q_Wk_h,   s_Wk_h);
    cudaGetSymbolAddress((void**)&q_Wk_l,   s_Wk_l);
    cudaGetSymbolAddress((void**)&q_Wr_h,   s_Wr_h);
    cudaGetSymbolAddress((void**)&q_Wr_l,   s_Wr_l);

    cudaFuncSetAttribute(gru_kernel,
                         cudaFuncAttributeMaxDynamicSharedMemorySize, GRU_SMEM);
    cudaFuncSetAttribute(hmma_kernel,
                         cudaFuncAttributeMaxDynamicSharedMemorySize, HMMA_SMEM);

    init_kernel<<<16, 256>>>();
    embed_split_kernel<<<NTOK, 128>>>(ids, embW);

    auto split = [&](const float* src, __nv_bfloat16* h, __nv_bfloat16* l, int n) {
        int n4 = n / 4;
        split_kernel<<<(n4 + 255) / 256, 256>>>(src, h, l, n4);
    };

    // Weight splits for tensor-core GEMMs
    split(embW, q_embW_h, q_embW_l, VDIM * EDIM);
    split(w_ih, q_wih_h,  q_wih_l,  3 * HDIM * EDIM);
    split(W1,   q_W1_h,   q_W1_l,   4 * EDIM * HDIM);
    split(W2,   q_W2_h,   q_W2_l,   EDIM * 4 * EDIM);
    split(Wq,   q_Wq_h,   q_Wq_l,   MDIM * HDIM);
    split(Wk,   q_Wk_h,   q_Wk_l,   MDIM * HDIM);
    split(Wr,   q_Wr_h,   q_Wr_l,   EDIM * EDIM);

    // xp = emb @ w_ih^T + b_ih   [2048, 3072]
    hmma_kernel<<<dim3(NTOK / 128, 3 * HDIM / 128), 256, HMMA_SMEM>>>(
        q_emb_h, q_emb_l, q_wih_h, q_wih_l, b_ih, p_xp,
        NTOK, 3 * HDIM, EDIM, EPI_F32, nullptr, nullptr, nullptr, nullptr);

    // Recurrent scan -> g_states (+ in-place split to s_st_h/l)
    gru_kernel<<<GRU_CTAS, GRU_THREADS, GRU_SMEM>>>(p_xp, w_hh, b_hh);

    gate_kernel<<<NTOK, 128>>>(Wg, bg);

    // hf = relu(states @ W1^T + b1)^2   [2048, 2048] -> split planes only
    hmma_kernel<<<dim3(NTOK / 128, 4 * EDIM / 128), 256, HMMA_SMEM>>>(
        q_st_h, q_st_l, q_W1_h, q_W1_l, b1, nullptr,
        NTOK, 4 * EDIM, HDIM, EPI_RELU2 | EPI_SPLIT,
        nullptr, nullptr, q_hf_h, q_hf_l);

    // base = hf @ W2^T + b2   [2048, 512] -> fp32 + split planes
    hmma_kernel<<<dim3(NTOK / 128, EDIM / 128), 256, HMMA_SMEM>>>(
        q_hf_h, q_hf_l, q_W2_h, q_W2_l, b2, p_base,
        NTOK, EDIM, 4 * EDIM, EPI_F32 | EPI_SPLIT,
        nullptr, nullptr, q_base_h, q_base_l);

    // comb = base + gate * relu(base @ Wr^T + br)  [2048, 512] -> split only
    hmma_kernel<<<dim3(NTOK / 128, EDIM / 128), 256, HMMA_SMEM>>>(
        q_base_h, q_base_l, q_Wr_h, q_Wr_l, br, nullptr,
        NTOK, EDIM, EDIM, EPI_GATE | EPI_SPLIT,
        p_base, p_gate, q_comb_h, q_comb_l);

    // q / k projections   [2048, 256] -> fp32
    hmma_kernel<<<dim3(NTOK / 128, MDIM / 128), 256, HMMA_SMEM>>>(
        q_st_h, q_st_l, q_Wq_h, q_Wq_l, bq, p_q,
        NTOK, MDIM, HDIM, EPI_F32, nullptr, nullptr, nullptr, nullptr);
    hmma_kernel<<<dim3(NTOK / 128, MDIM / 128), 256, HMMA_SMEM>>>(
        q_st_h, q_st_l, q_Wk_h, q_Wk_l, bk, p_k,
        NTOK, MDIM, HDIM, EPI_F32, nullptr, nullptr, nullptr, nullptr);

    // logits = comb @ emb_W^T + output_bias   [2048, 32000] -> d_out
    hmma_kernel<<<dim3(NTOK / 128, VDIM / 128), 256, HMMA_SMEM>>>(
        q_comb_h, q_comb_l, q_embW_h, q_embW_l, obias, out,
        NTOK, VDIM, EDIM, EPI_F32, nullptr, nullptr, nullptr, nullptr);

    // softmax + scatter-add of gated attention into logits
    attn_scatter_kernel<<<NTOK, 256>>>(ids, mscale, out);
}

// round 15
// speedup vs baseline: 1.4560x; 1.4560x over previous
#include <cuda_runtime.h>
#include <cuda_bf16.h>
#include <math.h>
#include <stdint.h>

// ---------------------------------------------------------------------------
// Problem constants
// ---------------------------------------------------------------------------
#define S_LEN 1024
#define BATCH 2
#define NTOK  2048          // B*S
#define EDIM  512
#define HDIM  1024
#define MDIM  256
#define VDIM  32000

// ---------------------------------------------------------------------------
// Scratch (device globals: the sanctioned alternative to cudaMalloc)
// ---------------------------------------------------------------------------
__device__ float g_xp[NTOK * 3 * HDIM];
__device__ float g_states[NTOK * HDIM];
__device__ float g_h[2 * BATCH * HDIM];
__device__ float g_hf[NTOK * 4 * EDIM];
__device__ float g_base[NTOK * EDIM];
__device__ float g_comb[NTOK * EDIM];
__device__ float g_gate[NTOK];
__device__ float g_q[NTOK * MDIM];
__device__ float g_k[NTOK * MDIM];
__device__ unsigned g_bar_cnt;

// Split (hi/lo bf16) planes for tensor-core GEMMs
__device__ __nv_bfloat16 s_embW_h[VDIM * EDIM],     s_embW_l[VDIM * EDIM];
__device__ __nv_bfloat16 s_emb_h [NTOK * EDIM],     s_emb_l [NTOK * EDIM];
__device__ __nv_bfloat16 s_wih_h [3 * HDIM * EDIM], s_wih_l [3 * HDIM * EDIM];
__device__ __nv_bfloat16 s_st_h  [NTOK * HDIM],     s_st_l  [NTOK * HDIM];
__device__ __nv_bfloat16 s_W1_h  [4 * EDIM * HDIM], s_W1_l  [4 * EDIM * HDIM];
__device__ __nv_bfloat16 s_hf_h  [NTOK * 4 * EDIM], s_hf_l  [NTOK * 4 * EDIM];
__device__ __nv_bfloat16 s_W2_h  [EDIM * 4 * EDIM], s_W2_l  [EDIM * 4 * EDIM];
__device__ __nv_bfloat16 s_comb_h[NTOK * EDIM],     s_comb_l[NTOK * EDIM];
__device__ __nv_bfloat16 s_Wq_h  [MDIM * HDIM],     s_Wq_l  [MDIM * HDIM];
__device__ __nv_bfloat16 s_Wk_h  [MDIM * HDIM],     s_Wk_l  [MDIM * HDIM];

// ---------------------------------------------------------------------------
// Init: zero recurrent state + reset grid barrier
// ---------------------------------------------------------------------------
__global__ void init_kernel() {
    int i = blockIdx.x * blockDim.x + threadIdx.x;
    if (i < 2 * BATCH * HDIM) g_h[i] = 0.f;
    if (i == 0) g_bar_cnt = 0u;
}

// ---------------------------------------------------------------------------
// Split helpers
// ---------------------------------------------------------------------------
__device__ __forceinline__ void split1(float x, __nv_bfloat16& h, __nv_bfloat16& l) {
    h = __float2bfloat16(x);
    l = __float2bfloat16(x - __bfloat162float(h));
}

// Fused embedding gather + hi/lo split
__global__ void embed_split_kernel(const int* __restrict__ ids,
                                   const float* __restrict__ embW) {
    int t = blockIdx.x;
    int c = threadIdx.x;                   // 128 threads, one float4 each
    int id = ids[t];
    float4 v = ((const float4*)embW)[(size_t)id * (EDIM / 4) + c];
    __nv_bfloat16 h0, h1, h2, h3, l0, l1, l2, l3;
    split1(v.x, h0, l0); split1(v.y, h1, l1);
    split1(v.z, h2, l2); split1(v.w, h3, l3);
    size_t o = (size_t)t * (EDIM / 2) + 2 * c;   // bf16x2 units
    ((__nv_bfloat162*)s_emb_h)[o]     = __nv_bfloat162(h0, h1);
    ((__nv_bfloat162*)s_emb_h)[o + 1] = __nv_bfloat162(h2, h3);
    ((__nv_bfloat162*)s_emb_l)[o]     = __nv_bfloat162(l0, l1);
    ((__nv_bfloat162*)s_emb_l)[o + 1] = __nv_bfloat162(l2, l3);
}

// Generic fp32 -> (hi, lo) bf16 split.  x = hi + lo + O(2^-18 x)
__global__ void __launch_bounds__(256) split_kernel(
    const float* __restrict__ src,
    __nv_bfloat16* __restrict__ hi, __nv_bfloat16* __restrict__ lo, int n4)
{
    int i = blockIdx.x * blockDim.x + threadIdx.x;
    if (i >= n4) return;
    float4 v = ((const float4*)src)[i];
    __nv_bfloat16 h0, h1, h2, h3, l0, l1, l2, l3;
    split1(v.x, h0, l0); split1(v.y, h1, l1);
    split1(v.z, h2, l2); split1(v.w, h3, l3);
    ((__nv_bfloat162*)hi)[2 * i]     = __nv_bfloat162(h0, h1);
    ((__nv_bfloat162*)hi)[2 * i + 1] = __nv_bfloat162(h2, h3);
    ((__nv_bfloat162*)lo)[2 * i]     = __nv_bfloat162(l0, l1);
    ((__nv_bfloat162*)lo)[2 * i + 1] = __nv_bfloat162(l2, l3);
}

// ---------------------------------------------------------------------------
// Tensor-core GEMM (error-compensated bf16 split) — R13 version, epilogue
// kept THIN (register-critical under __launch_bounds__(256,2); R14 showed
// fattening it causes spills into the main loop).
//   C[m][n] = sum_k A[m][k]*B[n][k] + bias[n]   (+ optional relu^2)
// computed as A_hi*B_hi + A_lo*B_hi + A_hi*B_lo  (lo*lo dropped, ~2^-18)
// Block 128x128, 8 warps (4m x 2n), warp tile 32x64, K-tile 32.
// cp.async double-buffered SMEM; grid x = M-tile (fastest) for B-tile L2 reuse.
// epi 0: +bias     epi 1: relu(x+bias)^2
// ---------------------------------------------------------------------------
__device__ __forceinline__ void ldsm4(uint32_t& r0, uint32_t& r1,
                                      uint32_t& r2, uint32_t& r3, uint32_t a) {
    asm volatile("ldmatrix.sync.aligned.m8n8.x4.shared.b16 {%0,%1,%2,%3}, [%4];"
                 : "=r"(r0), "=r"(r1), "=r"(r2), "=r"(r3) : "r"(a));
}
__device__ __forceinline__ void mma16816(float* d, const uint32_t* a,
                                         const uint32_t* b) {
    asm volatile(
        "mma.sync.aligned.m16n8k16.row.col.f32.bf16.bf16.f32 "
        "{%0,%1,%2,%3}, {%4,%5,%6,%7}, {%8,%9}, {%0,%1,%2,%3};"
        : "+f"(d[0]), "+f"(d[1]), "+f"(d[2]), "+f"(d[3])
        : "r"(a[0]), "r"(a[1]), "r"(a[2]), "r"(a[3]), "r"(b[0]), "r"(b[1]));
}
__device__ __forceinline__ void cpasync16(uint32_t saddr, const void* gaddr) {
    asm volatile("cp.async.cg.shared.global [%0], [%1], 16;"
                 :: "r"(saddr), "l"(gaddr));
}

#define HMMA_SMEM (2 * 4 * 128 * 40 * 2)   // 81920 bytes

__global__ void __launch_bounds__(256, 2) hmma_kernel(
    const __nv_bfloat16* __restrict__ Ahi, const __nv_bfloat16* __restrict__ Alo,
    const __nv_bfloat16* __restrict__ Bhi, const __nv_bfloat16* __restrict__ Blo,
    const float* __restrict__ bias, float* __restrict__ C,
    int M, int N, int K, int epi)
{
    extern __shared__ __nv_bfloat16 dynsm[];
    const uint32_t smem0 = (uint32_t)__cvta_generic_to_shared(dynsm);
    const int tid = threadIdx.x;
    const int lane = tid & 31, wid = tid >> 5;
    const int wm = wid & 3, wn = wid >> 2;
    const int row0 = blockIdx.x * 128, col0 = blockIdx.y * 128;

    float acc[2][8][4];
#pragma unroll
    for (int mi = 0; mi < 2; ++mi)
#pragma unroll
        for (int ni = 0; ni < 8; ++ni)
#pragma unroll
            for (int u = 0; u < 4; ++u) acc[mi][ni][u] = 0.f;

    const int rA = tid >> 2;            // 0..63
    const int ko = (tid & 3) * 8;       // 0,8,16,24

    const int rlA = (lane & 7) + ((lane >> 3) & 1) * 8;
    const int clA = (lane >> 4) * 8;
    const uint32_t aOff = (uint32_t)(((wm * 32 + rlA) * 40 + clA) * 2);
    const int rlB = (lane & 7) + (lane >= 16 ? 8 : 0);
    const int clB = ((lane >> 3) & 1) * 8;
    const uint32_t bOff = (uint32_t)(((wn * 64 + rlB) * 40 + clB) * 2);

    const int nkt = K >> 5;

    auto prefetch = [&](int kt) {
        const int k0 = kt << 5;
        const uint32_t sb = smem0 + (uint32_t)(kt & 1) * 40960u;
        const size_t ga0 = (size_t)(row0 + rA)      * K + k0 + ko;
        const size_t ga1 = (size_t)(row0 + rA + 64) * K + k0 + ko;
        const size_t gb0 = (size_t)(col0 + rA)      * K + k0 + ko;
        const size_t gb1 = (size_t)(col0 + rA + 64) * K + k0 + ko;
        const uint32_t s0 = sb + (uint32_t)((rA * 40 + ko) * 2);
        const uint32_t s1 = sb + (uint32_t)(((rA + 64) * 40 + ko) * 2);
        cpasync16(s0,          Ahi + ga0); cpasync16(s1,          Ahi + ga1);
        cpasync16(s0 + 10240u, Alo + ga0); cpasync16(s1 + 10240u, Alo + ga1);
        cpasync16(s0 + 20480u, Bhi + gb0); cpasync16(s1 + 20480u, Bhi + gb1);
        cpasync16(s0 + 30720u, Blo + gb0); cpasync16(s1 + 30720u, Blo + gb1);
    };

    prefetch(0);
    asm volatile("cp.async.commit_group;");

    for (int kt = 0; kt < nkt; ++kt) {
        if (kt + 1 < nkt) {
            prefetch(kt + 1);
            asm volatile("cp.async.commit_group;");
            asm volatile("cp.async.wait_group 1;");
        } else {
            asm volatile("cp.async.wait_group 0;");
        }
        __syncthreads();
        const uint32_t base = smem0 + (uint32_t)(kt & 1) * 40960u;
#pragma unroll
        for (int ks = 0; ks < 2; ++ks) {
            uint32_t ah[2][4], al[2][4];
#pragma unroll
            for (int mi = 0; mi < 2; ++mi) {
                uint32_t ka = base + aOff + (uint32_t)(mi * 1280 + ks * 32);
                ldsm4(ah[mi][0], ah[mi][1], ah[mi][2], ah[mi][3], ka);
                ldsm4(al[mi][0], al[mi][1], al[mi][2], al[mi][3], ka + 10240u);
            }
#pragma unroll
            for (int np = 0; np < 4; ++np) {
                uint32_t kb = base + 20480u + bOff +
                              (uint32_t)(np * 1280 + ks * 32);
                uint32_t bh[4], bl[4];
                ldsm4(bh[0], bh[1], bh[2], bh[3], kb);
                ldsm4(bl[0], bl[1], bl[2], bl[3], kb + 10240u);
#pragma unroll
                for (int mi = 0; mi < 2; ++mi) {
                    mma16816(acc[mi][2 * np],     ah[mi], bh);
                    mma16816(acc[mi][2 * np],     al[mi], bh);
                    mma16816(acc[mi][2 * np],     ah[mi], bl);
                    mma16816(acc[mi][2 * np + 1], ah[mi], bh + 2);
                    mma16816(acc[mi][2 * np + 1], al[mi], bh + 2);
                    mma16816(acc[mi][2 * np + 1], ah[mi], bl + 2);
                }
            }
        }
        __syncthreads();
    }

    // Epilogue (thin!)
    const int g = lane >> 2, tg = lane & 3;
#pragma unroll
    for (int mi = 0; mi < 2; ++mi) {
        const int r = row0 + wm * 32 + mi * 16 + g;
#pragma unroll
        for (int ni = 0; ni < 8; ++ni) {
            const int c = col0 + wn * 64 + ni * 8 + tg * 2;
            const float b0 = bias[c], b1 = bias[c + 1];
            float v00 = acc[mi][ni][0] + b0, v01 = acc[mi][ni][1] + b1;
            float v10 = acc[mi][ni][2] + b0, v11 = acc[mi][ni][3] + b1;
            if (epi == 1) {
                v00 = fmaxf(v00, 0.f); v00 *= v00;
                v01 = fmaxf(v01, 0.f); v01 *= v01;
                v10 = fmaxf(v10, 0.f); v10 *= v10;
                v11 = fmaxf(v11, 0.f); v11 *= v11;
            }
            *(float2*)(C + (size_t)r * N + c)       = make_float2(v00, v01);
            *(float2*)(C + (size_t)(r + 8) * N + c) = make_float2(v10, v11);
        }
    }
}

// ---------------------------------------------------------------------------
// Plain fp32 SGEMM (comb only now).
// epi 0: +bias   epi 2: auxb[m][n] + auxg[m]*relu(x+bias)
// ---------------------------------------------------------------------------
__global__ void __launch_bounds__(256) sgemm_kernel(
    const float* __restrict__ A, const float* __restrict__ B,
    const float* __restrict__ bias, float* __restrict__ C,
    int M, int N, int K, int epi,
    const float* __restrict__ auxb, const float* __restrict__ auxg)
{
    __shared__ float As[16][132];
    __shared__ float Bs[16][132];
    const int tid = threadIdx.x;
    const int tx = tid & 15, ty = tid >> 4;
    const int row0 = blockIdx.y * 128, col0 = blockIdx.x * 128;

    float acc[8][8];
#pragma unroll
    for (int i = 0; i < 8; ++i)
#pragma unroll
        for (int j = 0; j < 8; ++j) acc[i][j] = 0.f;

    for (int k0 = 0; k0 < K; k0 += 16) {
#pragma unroll
        for (int i = 0; i < 2; ++i) {
            int v = tid + i * 256;
            int r = v >> 2;
            int kq = (v & 3) << 2;
            float4 av = *(const float4*)(A + (size_t)(row0 + r) * K + k0 + kq);
            As[kq + 0][r] = av.x; As[kq + 1][r] = av.y;
            As[kq + 2][r] = av.z; As[kq + 3][r] = av.w;
            float4 bv = *(const float4*)(B + (size_t)(col0 + r) * K + k0 + kq);
            Bs[kq + 0][r] = bv.x; Bs[kq + 1][r] = bv.y;
            Bs[kq + 2][r] = bv.z; Bs[kq + 3][r] = bv.w;
        }
        __syncthreads();
#pragma unroll
        for (int k = 0; k < 16; ++k) {
            float4 a0 = *(const float4*)&As[k][ty * 8];
            float4 a1 = *(const float4*)&As[k][ty * 8 + 4];
            float4 b0 = *(const float4*)&Bs[k][tx * 8];
            float4 b1 = *(const float4*)&Bs[k][tx * 8 + 4];
            float a[8] = {a0.x, a0.y, a0.z, a0.w, a1.x, a1.y, a1.z, a1.w};
            float b[8] = {b0.x, b0.y, b0.z, b0.w, b1.x, b1.y, b1.z, b1.w};
#pragma unroll
            for (int i = 0; i < 8; ++i)
#pragma unroll
                for (int j = 0; j < 8; ++j)
                    acc[i][j] = fmaf(a[i], b[j], acc[i][j]);
        }
        __syncthreads();
    }

#pragma unroll
    for (int i = 0; i < 8; ++i) {
        int m = row0 + ty * 8 + i;
#pragma unroll
        for (int j = 0; j < 8; j += 4) {
            int n = col0 + tx * 8 + j;
            float o[4];
#pragma unroll
            for (int u = 0; u < 4; ++u) {
                float x = acc[i][j + u] + bias[n + u];
                if (epi == 2)
                    x = auxb[(size_t)m * N + n + u] + auxg[m] * fmaxf(x, 0.f);
                o[u] = x;
            }
            *(float4*)(C + (size_t)m * N + n) = make_float4(o[0], o[1], o[2], o[3]);
        }
    }
}

// ---------------------------------------------------------------------------
// GRU: persistent kernel (R13 version, no in-place split — that was part of
// the R14 regression cluster).
// ---------------------------------------------------------------------------
#define GRU_CTAS    128
#define GRU_THREADS 256
#define GRU_SMEM    ((24 * HDIM + BATCH * HDIM) * 4)

__device__ __forceinline__ float warp_sum(float v) {
#pragma unroll
    for (int o = 16; o; o >>= 1) v += __shfl_xor_sync(0xffffffffu, v, o);
    return v;
}

__global__ void __launch_bounds__(GRU_THREADS, 1) gru_kernel(
    const float* __restrict__ xp, const float* __restrict__ w_hh,
    const float* __restrict__ b_hh)
{
    extern __shared__ float sm[];
    float* wsm = sm;                       // [24][HDIM], row = gate*8 + jl
    float* hsm = sm + 24 * HDIM;           // [BATCH][HDIM]
    const int tid = threadIdx.x;
    const int w = tid >> 5, lane = tid & 31;
    const int j0 = blockIdx.x * 8;

    for (int v = tid; v < 24 * (HDIM / 4); v += GRU_THREADS) {
        int rowl = v / (HDIM / 4);
        int c4 = v % (HDIM / 4);
        int g = rowl >> 3, jl = rowl & 7;
        ((float4*)wsm)[(size_t)rowl * (HDIM / 4) + c4] =
            ((const float4*)w_hh)[(size_t)(g * HDIM + j0 + jl) * (HDIM / 4) + c4];
    }
    const int j = j0 + w;
    const float bhr = b_hh[j];
    const float bhz = b_hh[HDIM + j];
    const float bhn = b_hh[2 * HDIM + j];
    __syncthreads();

    float xv0 = 0.f, xv1 = 0.f, xv2 = 0.f;
    if (lane < 2) {
        const float* xpt = xp + ((size_t)lane * S_LEN) * (3 * HDIM);
        xv0 = xpt[j]; xv1 = xpt[HDIM + j]; xv2 = xpt[2 * HDIM + j];
    }

    for (int s = 0; s < S_LEN; ++s) {
        const float* h_in = g_h + (s & 1) * (BATCH * HDIM);
        float* h_out      = g_h + ((s + 1) & 1) * (BATCH * HDIM);

        for (int v = tid; v < (BATCH * HDIM) / 4; v += GRU_THREADS)
            ((float4*)hsm)[v] = __ldcg(((const float4*)h_in) + v);
        __syncthreads();

        float xn0 = 0.f, xn1 = 0.f, xn2 = 0.f;
        if (lane < 2 && s + 1 < S_LEN) {
            const float* xpt = xp + ((size_t)lane * S_LEN + s + 1) * (3 * HDIM);
            xn0 = __ldg(xpt + j);
            xn1 = __ldg(xpt + HDIM + j);
            xn2 = __ldg(xpt + 2 * HDIM + j);
        }

        float4 H0[8], H1[8];
#pragma unroll
        for (int c = 0; c < 8; ++c) {
            H0[c] = ((const float4*)hsm)[lane + 32 * c];
            H1[c] = ((const float4*)(hsm + HDIM))[lane + 32 * c];
        }
        float acc[3][2];
#pragma unroll
        for (int g = 0; g < 3; ++g) {
            const float4* wp = (const float4*)(wsm + (size_t)(g * 8 + w) * HDIM);
            float s0a = 0.f, s0b = 0.f, s1a = 0.f, s1b = 0.f;
#pragma unroll
            for (int c = 0; c < 8; ++c) {
                float4 wv = wp[lane + 32 * c];
                s0a = fmaf(wv.x, H0[c].x, s0a); s0b = fmaf(wv.y, H0[c].y, s0b);
                s0a = fmaf(wv.z, H0[c].z, s0a); s0b = fmaf(wv.w, H0[c].w, s0b);
                s1a = fmaf(wv.x, H1[c].x, s1a); s1b = fmaf(wv.y, H1[c].y, s1b);
                s1a = fmaf(wv.z, H1[c].z, s1a); s1b = fmaf(wv.w, H1[c].w, s1b);
            }
            acc[g][0] = warp_sum(s0a + s0b);   // result in ALL lanes
            acc[g][1] = warp_sum(s1a + s1b);
        }

        if (lane < 2) {
            const int b = lane;
            size_t t = (size_t)b * S_LEN + s;
            float r = 1.f / (1.f + __expf(-(xv0 + acc[0][b] + bhr)));
            float z = 1.f / (1.f + __expf(-(xv1 + acc[1][b] + bhz)));
            float n = tanhf(xv2 + r * (acc[2][b] + bhn));
            float hp = hsm[b * HDIM + j];
            float hn2 = (1.f - z) * n + z * hp;
            g_states[t * HDIM + j] = hn2;
            __stcg(h_out + b * HDIM + j, hn2);
        }
        xv0 = xn0; xv1 = xn1; xv2 = xn2;
        __syncthreads();

        // --- grid barrier: monotonic counter, direct poll ---
        if (tid == 0) {
            __threadfence();
            atomicAdd(&g_bar_cnt, 1u);
            const unsigned target = (unsigned)GRU_CTAS * (unsigned)(s + 1);
            while (*((volatile unsigned*)&g_bar_cnt) < target) { }
            __threadfence();
        }
        __syncthreads();
    }
}

// ---------------------------------------------------------------------------
// gate[t] = sigmoid(states[t] . Wg + bg)
// ---------------------------------------------------------------------------
__global__ void gate_kernel(const float* __restrict__ Wg,
                            const float* __restrict__ bg) {
    int t = blockIdx.x;
    int tid = threadIdx.x;
    const float4* sp = (const float4*)(g_states + (size_t)t * HDIM);
    const float4* wp = (const float4*)Wg;
    float s = 0.f;
    for (int c = tid; c < HDIM / 4; c += 128) {
        float4 a = sp[c], ww = wp[c];
        s += a.x * ww.x + a.y * ww.y + a.z * ww.z + a.w * ww.w;
    }
    __shared__ float red[128];
    red[tid] = s; __syncthreads();
    for (int k = 64; k; k >>= 1) {
        if (tid < k) red[tid] += red[tid + k];
        __syncthreads();
    }
    if (tid == 0) g_gate[t] = 1.f / (1.f + expf(-(red[0] + bg[0])));
}

// ---------------------------------------------------------------------------
// Split states fp32 -> hi/lo planes (separate kernel; keeps GRU tail thin)
// ---------------------------------------------------------------------------

// ---------------------------------------------------------------------------
// Fused attention softmax + scatter-add into logits
// ---------------------------------------------------------------------------
__global__ void __launch_bounds__(256) attn_scatter_kernel(
    const int* __restrict__ ids, const float* __restrict__ mscale,
    float* __restrict__ out)
{
    int bq = blockIdx.x;
    int b = bq >> 10, qpos = bq & 1023;
    if (qpos == 0) return;
    int tid = threadIdx.x;

    __shared__ float qv[MDIM];
    __shared__ float red[256];
    if (tid < MDIM) qv[tid] = g_q[(size_t)bq * MDIM + tid];
    __syncthreads();

    const int nk = qpos;
    float sc[4];
    int cnt = 0;
    float mx = -1e30f;
    for (int kp = tid; kp < nk; kp += 256) {
        const float4* kr = (const float4*)(g_k + (size_t)(b * S_LEN + kp) * MDIM);
        float d = 0.f;
#pragma unroll 16
        for (int c = 0; c < MDIM / 4; ++c) {
            float4 kv = kr[c];
            float4 qq = ((const float4*)qv)[c];
            d += kv.x * qq.x + kv.y * qq.y + kv.z * qq.z + kv.w * qq.w;
        }
        d *= 0.0625f;
        sc[cnt++] = d;
        mx = fmaxf(mx, d);
    }
    red[tid] = mx; __syncthreads();
    for (int k = 128; k; k >>= 1) {
        if (tid < k) red[tid] = fmaxf(red[tid], red[tid + k]);
        __syncthreads();
    }
    mx = red[0]; __syncthreads();

    float sum = 0.f;
    for (int i = 0; i < cnt; ++i) { sc[i] = expf(sc[i] - mx); sum += sc[i]; }
    red[tid] = sum; __syncthreads();
    for (int k = 128; k; k >>= 1) {
        if (tid < k) red[tid] += red[tid + k];
        __syncthreads();
    }
    sum = red[0];

    float coef = g_gate[bq] * mscale[0] / sum;
    int i2 = 0;
    for (int kp = tid; kp < nk; kp += 256) {
        int vid = ids[b * S_LEN + kp];
        atomicAdd(out + (size_t)bq * VDIM + vid, sc[i2++] * coef);
    }
}

// ---------------------------------------------------------------------------
// Host launcher
// ---------------------------------------------------------------------------
extern "C" void kernel_launch(void* const* d_in, const int* in_sizes, int n_in,
                              void* d_out, int out_size) {
    (void)in_sizes; (void)n_in; (void)out_size;
    const int*   ids    = (const int*)d_in[0];
    const float* embW   = (const float*)d_in[1];
    const float* w_ih   = (const float*)d_in[2];
    const float* w_hh   = (const float*)d_in[3];
    const float* b_ih   = (const float*)d_in[4];
    const float* b_hh   = (const float*)d_in[5];
    const float* Wq     = (const float*)d_in[6];
    const float* bq     = (const float*)d_in[7];
    const float* Wk     = (const float*)d_in[8];
    const float* bk     = (const float*)d_in[9];
    const float* Wg     = (const float*)d_in[10];
    const float* bg     = (const float*)d_in[11];
    const float* W1     = (const float*)d_in[12];
    const float* b1     = (const float*)d_in[13];
    const float* W2     = (const float*)d_in[14];
    const float* b2     = (const float*)d_in[15];
    const float* Wr     = (const float*)d_in[16];
    const float* br     = (const float*)d_in[17];
    const float* mscale = (const float*)d_in[18];
    const float* obias  = (const float*)d_in[19];
    float* out = (float*)d_out;

    float *p_xp, *p_states, *p_hf, *p_base, *p_comb, *p_gate, *p_q, *p_k;
    cudaGetSymbolAddress((void**)&p_xp,     g_xp);
    cudaGetSymbolAddress((void**)&p_states, g_states);
    cudaGetSymbolAddress((void**)&p_hf,     g_hf);
    cudaGetSymbolAddress((void**)&p_base,   g_base);
    cudaGetSymbolAddress((void**)&p_comb,   g_comb);
    cudaGetSymbolAddress((void**)&p_gate,   g_gate);
    cudaGetSymbolAddress((void**)&p_q,      g_q);
    cudaGetSymbolAddress((void**)&p_k,      g_k);

    __nv_bfloat16 *q_embW_h, *q_embW_l, *q_emb_h, *q_emb_l, *q_wih_h, *q_wih_l,
                  *q_st_h, *q_st_l, *q_W1_h, *q_W1_l, *q_hf_h, *q_hf_l,
                  *q_W2_h, *q_W2_l, *q_comb_h, *q_comb_l,
                  *q_Wq_h, *q_Wq_l, *q_Wk_h, *q_Wk_l;
    cudaGetSymbolAddress((void**)&q_embW_h, s_embW_h);
    cudaGetSymbolAddress((void**)&q_embW_l, s_embW_l);
    cudaGetSymbolAddress((void**)&q_emb_h,  s_emb_h);
    cudaGetSymbolAddress((void**)&q_emb_l,  s_emb_l);
    cudaGetSymbolAddress((void**)&q_wih_h,  s_wih_h);
    cudaGetSymbolAddress((void**)&q_wih_l,  s_wih_l);
    cudaGetSymbolAddress((void**)&q_st_h,   s_st_h);
    cudaGetSymbolAddress((void**)&q_st_l,   s_st_l);
    cudaGetSymbolAddress((void**)&q_W1_h,   s_W1_h);
    cudaGetSymbolAddress((void**)&q_W1_l,   s_W1_l);
    cudaGetSymbolAddress((void**)&q_hf_h,   s_hf_h);
    cudaGetSymbolAddress((void**)&q_hf_l,   s_hf_l);
    cudaGetSymbolAddress((void**)&q_W2_h,   s_W2_h);
    cudaGetSymbolAddress((void**)&q_W2_l,   s_W2_l);
    cudaGetSymbolAddress((void**)&q_comb_h, s_comb_h);
    cudaGetSymbolAddress((void**)&q_comb_l, s_comb_l);
    cudaGetSymbolAddress((void**)&q_Wq_h,   s_Wq_h);
    cudaGetSymbolAddress((void**)&q_Wq_l,   s_Wq_l);
    cudaGetSymbolAddress((void**)&q_Wk_h,   s_Wk_h);
    cudaGetSymbolAddress((void**)&q_Wk_l,   s_Wk_l);

    cudaFuncSetAttribute(gru_kernel,
                         cudaFuncAttributeMaxDynamicSharedMemorySize, GRU_SMEM);
    cudaFuncSetAttribute(hmma_kernel,
                         cudaFuncAttributeMaxDynamicSharedMemorySize, HMMA_SMEM);

    init_kernel<<<16, 256>>>();
    embed_split_kernel<<<NTOK, 128>>>(ids, embW);

    auto split = [&](const float* src, __nv_bfloat16* h, __nv_bfloat16* l, int n) {
        int n4 = n / 4;
        split_kernel<<<(n4 + 255) / 256, 256>>>(src, h, l, n4);
    };

    // Weight splits for tensor-core GEMMs
    split(embW, q_embW_h, q_embW_l, VDIM * EDIM);
    split(w_ih, q_wih_h,  q_wih_l,  3 * HDIM * EDIM);
    split(W1,   q_W1_h,   q_W1_l,   4 * EDIM * HDIM);
    split(W2,   q_W2_h,   q_W2_l,   EDIM * 4 * EDIM);
    split(Wq,   q_Wq_h,   q_Wq_l,   MDIM * HDIM);
    split(Wk,   q_Wk_h,   q_Wk_l,   MDIM * HDIM);

    // xp = emb @ w_ih^T + b_ih   [2048, 3072]   (grid x = M-tiles)
    hmma_kernel<<<dim3(NTOK / 128, 3 * HDIM / 128), 256, HMMA_SMEM>>>(
        q_emb_h, q_emb_l, q_wih_h, q_wih_l, b_ih, p_xp, NTOK, 3 * HDIM, EDIM, 0);

    // Recurrent scan -> g_states
    gru_kernel<<<GRU_CTAS, GRU_THREADS, GRU_SMEM>>>(p_xp, w_hh, b_hh);

    gate_kernel<<<NTOK, 128>>>(Wg, bg);
    split(p_states, q_st_h, q_st_l, NTOK * HDIM);

    // hf = relu(states @ W1^T + b1)^2   [2048, 2048]
    hmma_kernel<<<dim3(NTOK / 128, 4 * EDIM / 128), 256, HMMA_SMEM>>>(
        q_st_h, q_st_l, q_W1_h, q_W1_l, b1, p_hf, NTOK, 4 * EDIM, HDIM, 1);
    split(p_hf, q_hf_h, q_hf_l, NTOK * 4 * EDIM);

    // base = hf @ W2^T + b2             [2048, 512]
    hmma_kernel<<<dim3(NTOK / 128, EDIM / 128), 256, HMMA_SMEM>>>(
        q_hf_h, q_hf_l, q_W2_h, q_W2_l, b2, p_base, NTOK, EDIM, 4 * EDIM, 0);

    // comb = base + gate * relu(base @ Wr^T + br)   [2048, 512]
    sgemm_kernel<<<dim3(EDIM / 128, NTOK / 128), 256>>>(
        p_base, Wr, br, p_comb, NTOK, EDIM, EDIM, 2, p_base, p_gate);

    // q / k projections [2048, 256] — now on hmma (same kernel, epi 0)
    hmma_kernel<<<dim3(NTOK / 128, MDIM / 128), 256, HMMA_SMEM>>>(
        q_st_h, q_st_l, q_Wq_h, q_Wq_l, bq, p_q, NTOK, MDIM, HDIM, 0);
    hmma_kernel<<<dim3(NTOK / 128, MDIM / 128), 256, HMMA_SMEM>>>(
        q_st_h, q_st_l, q_Wk_h, q_Wk_l, bk, p_k, NTOK, MDIM, HDIM, 0);

    split(p_comb, q_comb_h, q_comb_l, NTOK * EDIM);

    // logits = comb @ emb_W^T + output_bias   [2048, 32000] -> d_out
    hmma_kernel<<<dim3(NTOK / 128, VDIM / 128), 256, HMMA_SMEM>>>(
        q_comb_h, q_comb_l, q_embW_h, q_embW_l, obias, out, NTOK, VDIM, EDIM, 0);

    // softmax + scatter-add of gated attention into logits
    attn_scatter_kernel<<<NTOK, 256>>>(ids, mscale, out);
}

// round 16
// speedup vs baseline: 1.5540x; 1.0673x over previous
#include <cuda_runtime.h>
#include <cuda_bf16.h>
#include <math.h>
#include <stdint.h>

// ---------------------------------------------------------------------------
// Problem constants
// ---------------------------------------------------------------------------
#define S_LEN 1024
#define BATCH 2
#define NTOK  2048          // B*S
#define EDIM  512
#define HDIM  1024
#define MDIM  256
#define VDIM  32000

// ---------------------------------------------------------------------------
// Scratch (device globals: the sanctioned alternative to cudaMalloc)
// ---------------------------------------------------------------------------
__device__ float g_xp[NTOK * 3 * HDIM];
__device__ float g_states[NTOK * HDIM];
__device__ float g_h[2 * BATCH * HDIM];
__device__ float g_hf[NTOK * 4 * EDIM];
__device__ float g_base[NTOK * EDIM];
__device__ float g_comb[NTOK * EDIM];
__device__ float g_gate[NTOK];
__device__ float g_q[NTOK * MDIM];
__device__ float g_k[NTOK * MDIM];
__device__ float g_sc[(size_t)BATCH * S_LEN * S_LEN];   // 8 MB score matrix
__device__ float g_zero[S_LEN];                          // zero bias
__device__ unsigned g_bar_cnt;

// Split (hi/lo bf16) planes for tensor-core GEMMs
__device__ __nv_bfloat16 s_embW_h[VDIM * EDIM],     s_embW_l[VDIM * EDIM];
__device__ __nv_bfloat16 s_emb_h [NTOK * EDIM],     s_emb_l [NTOK * EDIM];
__device__ __nv_bfloat16 s_wih_h [3 * HDIM * EDIM], s_wih_l [3 * HDIM * EDIM];
__device__ __nv_bfloat16 s_st_h  [NTOK * HDIM],     s_st_l  [NTOK * HDIM];
__device__ __nv_bfloat16 s_W1_h  [4 * EDIM * HDIM], s_W1_l  [4 * EDIM * HDIM];
__device__ __nv_bfloat16 s_hf_h  [NTOK * 4 * EDIM], s_hf_l  [NTOK * 4 * EDIM];
__device__ __nv_bfloat16 s_W2_h  [EDIM * 4 * EDIM], s_W2_l  [EDIM * 4 * EDIM];
__device__ __nv_bfloat16 s_comb_h[NTOK * EDIM],     s_comb_l[NTOK * EDIM];
__device__ __nv_bfloat16 s_Wq_h  [MDIM * HDIM],     s_Wq_l  [MDIM * HDIM];
__device__ __nv_bfloat16 s_Wk_h  [MDIM * HDIM],     s_Wk_l  [MDIM * HDIM];
__device__ __nv_bfloat16 s_qs_h  [NTOK * MDIM],     s_qs_l  [NTOK * MDIM];
__device__ __nv_bfloat16 s_ks_h  [NTOK * MDIM],     s_ks_l  [NTOK * MDIM];

// ---------------------------------------------------------------------------
// Init: zero recurrent state + zero bias + reset grid barrier
// ---------------------------------------------------------------------------
__global__ void init_kernel() {
    int i = blockIdx.x * blockDim.x + threadIdx.x;
    if (i < 2 * BATCH * HDIM) g_h[i] = 0.f;
    if (i < S_LEN) g_zero[i] = 0.f;
    if (i == 0) g_bar_cnt = 0u;
}

// ---------------------------------------------------------------------------
// Split helpers
// ---------------------------------------------------------------------------
__device__ __forceinline__ void split1(float x, __nv_bfloat16& h, __nv_bfloat16& l) {
    h = __float2bfloat16(x);
    l = __float2bfloat16(x - __bfloat162float(h));
}

// Fused embedding gather + hi/lo split
__global__ void embed_split_kernel(const int* __restrict__ ids,
                                   const float* __restrict__ embW) {
    int t = blockIdx.x;
    int c = threadIdx.x;                   // 128 threads, one float4 each
    int id = ids[t];
    float4 v = ((const float4*)embW)[(size_t)id * (EDIM / 4) + c];
    __nv_bfloat16 h0, h1, h2, h3, l0, l1, l2, l3;
    split1(v.x, h0, l0); split1(v.y, h1, l1);
    split1(v.z, h2, l2); split1(v.w, h3, l3);
    size_t o = (size_t)t * (EDIM / 2) + 2 * c;   // bf16x2 units
    ((__nv_bfloat162*)s_emb_h)[o]     = __nv_bfloat162(h0, h1);
    ((__nv_bfloat162*)s_emb_h)[o + 1] = __nv_bfloat162(h2, h3);
    ((__nv_bfloat162*)s_emb_l)[o]     = __nv_bfloat162(l0, l1);
    ((__nv_bfloat162*)s_emb_l)[o + 1] = __nv_bfloat162(l2, l3);
}

// Generic fp32 -> (hi, lo) bf16 split.  x = hi + lo + O(2^-18 x)
__global__ void __launch_bounds__(256) split_kernel(
    const float* __restrict__ src,
    __nv_bfloat16* __restrict__ hi, __nv_bfloat16* __restrict__ lo, int n4)
{
    int i = blockIdx.x * blockDim.x + threadIdx.x;
    if (i >= n4) return;
    float4 v = ((const float4*)src)[i];
    __nv_bfloat16 h0, h1, h2, h3, l0, l1, l2, l3;
    split1(v.x, h0, l0); split1(v.y, h1, l1);
    split1(v.z, h2, l2); split1(v.w, h3, l3);
    ((__nv_bfloat162*)hi)[2 * i]     = __nv_bfloat162(h0, h1);
    ((__nv_bfloat162*)hi)[2 * i + 1] = __nv_bfloat162(h2, h3);
    ((__nv_bfloat162*)lo)[2 * i]     = __nv_bfloat162(l0, l1);
    ((__nv_bfloat162*)lo)[2 * i + 1] = __nv_bfloat162(l2, l3);
}

// ---------------------------------------------------------------------------
// Tensor-core GEMM (error-compensated bf16 split) — epilogue kept THIN
// (register-critical under __launch_bounds__(256,2); R14 proved fattening it
// spills into the main loop).
//   C[m][n] = sum_k A[m][k]*B[n][k] + bias[n]   (+ optional relu^2)
// Block 128x128, 8 warps (4m x 2n), warp tile 32x64, K-tile 32.
// cp.async double-buffered SMEM; grid x = M-tile (fastest) for B-tile L2 reuse.
// epi 0: +bias     epi 1: relu(x+bias)^2
// ---------------------------------------------------------------------------
__device__ __forceinline__ void ldsm4(uint32_t& r0, uint32_t& r1,
                                      uint32_t& r2, uint32_t& r3, uint32_t a) {
    asm volatile("ldmatrix.sync.aligned.m8n8.x4.shared.b16 {%0,%1,%2,%3}, [%4];"
                 : "=r"(r0), "=r"(r1), "=r"(r2), "=r"(r3) : "r"(a));
}
__device__ __forceinline__ void mma16816(float* d, const uint32_t* a,
                                         const uint32_t* b) {
    asm volatile(
        "mma.sync.aligned.m16n8k16.row.col.f32.bf16.bf16.f32 "
        "{%0,%1,%2,%3}, {%4,%5,%6,%7}, {%8,%9}, {%0,%1,%2,%3};"
        : "+f"(d[0]), "+f"(d[1]), "+f"(d[2]), "+f"(d[3])
        : "r"(a[0]), "r"(a[1]), "r"(a[2]), "r"(a[3]), "r"(b[0]), "r"(b[1]));
}
__device__ __forceinline__ void cpasync16(uint32_t saddr, const void* gaddr) {
    asm volatile("cp.async.cg.shared.global [%0], [%1], 16;"
                 :: "r"(saddr), "l"(gaddr));
}

#define HMMA_SMEM (2 * 4 * 128 * 40 * 2)   // 81920 bytes

__global__ void __launch_bounds__(256, 2) hmma_kernel(
    const __nv_bfloat16* __restrict__ Ahi, const __nv_bfloat16* __restrict__ Alo,
    const __nv_bfloat16* __restrict__ Bhi, const __nv_bfloat16* __restrict__ Blo,
    const float* __restrict__ bias, float* __restrict__ C,
    int M, int N, int K, int epi)
{
    extern __shared__ __nv_bfloat16 dynsm[];
    const uint32_t smem0 = (uint32_t)__cvta_generic_to_shared(dynsm);
    const int tid = threadIdx.x;
    const int lane = tid & 31, wid = tid >> 5;
    const int wm = wid & 3, wn = wid >> 2;
    const int row0 = blockIdx.x * 128, col0 = blockIdx.y * 128;

    float acc[2][8][4];
#pragma unroll
    for (int mi = 0; mi < 2; ++mi)
#pragma unroll
        for (int ni = 0; ni < 8; ++ni)
#pragma unroll
            for (int u = 0; u < 4; ++u) acc[mi][ni][u] = 0.f;

    const int rA = tid >> 2;            // 0..63
    const int ko = (tid & 3) * 8;       // 0,8,16,24

    const int rlA = (lane & 7) + ((lane >> 3) & 1) * 8;
    const int clA = (lane >> 4) * 8;
    const uint32_t aOff = (uint32_t)(((wm * 32 + rlA) * 40 + clA) * 2);
    const int rlB = (lane & 7) + (lane >= 16 ? 8 : 0);
    const int clB = ((lane >> 3) & 1) * 8;
    const uint32_t bOff = (uint32_t)(((wn * 64 + rlB) * 40 + clB) * 2);

    const int nkt = K >> 5;

    auto prefetch = [&](int kt) {
        const int k0 = kt << 5;
        const uint32_t sb = smem0 + (uint32_t)(kt & 1) * 40960u;
        const size_t ga0 = (size_t)(row0 + rA)      * K + k0 + ko;
        const size_t ga1 = (size_t)(row0 + rA + 64) * K + k0 + ko;
        const size_t gb0 = (size_t)(col0 + rA)      * K + k0 + ko;
        const size_t gb1 = (size_t)(col0 + rA + 64) * K + k0 + ko;
        const uint32_t s0 = sb + (uint32_t)((rA * 40 + ko) * 2);
        const uint32_t s1 = sb + (uint32_t)(((rA + 64) * 40 + ko) * 2);
        cpasync16(s0,          Ahi + ga0); cpasync16(s1,          Ahi + ga1);
        cpasync16(s0 + 10240u, Alo + ga0); cpasync16(s1 + 10240u, Alo + ga1);
        cpasync16(s0 + 20480u, Bhi + gb0); cpasync16(s1 + 20480u, Bhi + gb1);
        cpasync16(s0 + 30720u, Blo + gb0); cpasync16(s1 + 30720u, Blo + gb1);
    };

    prefetch(0);
    asm volatile("cp.async.commit_group;");

    for (int kt = 0; kt < nkt; ++kt) {
        if (kt + 1 < nkt) {
            prefetch(kt + 1);
            asm volatile("cp.async.commit_group;");
            asm volatile("cp.async.wait_group 1;");
        } else {
            asm volatile("cp.async.wait_group 0;");
        }
        __syncthreads();
        const uint32_t base = smem0 + (uint32_t)(kt & 1) * 40960u;
#pragma unroll
        for (int ks = 0; ks < 2; ++ks) {
            uint32_t ah[2][4], al[2][4];
#pragma unroll
            for (int mi = 0; mi < 2; ++mi) {
                uint32_t ka = base + aOff + (uint32_t)(mi * 1280 + ks * 32);
                ldsm4(ah[mi][0], ah[mi][1], ah[mi][2], ah[mi][3], ka);
                ldsm4(al[mi][0], al[mi][1], al[mi][2], al[mi][3], ka + 10240u);
            }
#pragma unroll
            for (int np = 0; np < 4; ++np) {
                uint32_t kb = base + 20480u + bOff +
                              (uint32_t)(np * 1280 + ks * 32);
                uint32_t bh[4], bl[4];
                ldsm4(bh[0], bh[1], bh[2], bh[3], kb);
                ldsm4(bl[0], bl[1], bl[2], bl[3], kb + 10240u);
#pragma unroll
                for (int mi = 0; mi < 2; ++mi) {
                    mma16816(acc[mi][2 * np],     ah[mi], bh);
                    mma16816(acc[mi][2 * np],     al[mi], bh);
                    mma16816(acc[mi][2 * np],     ah[mi], bl);
                    mma16816(acc[mi][2 * np + 1], ah[mi], bh + 2);
                    mma16816(acc[mi][2 * np + 1], al[mi], bh + 2);
                    mma16816(acc[mi][2 * np + 1], ah[mi], bl + 2);
                }
            }
        }
        __syncthreads();
    }

    // Epilogue (thin!)
    const int g = lane >> 2, tg = lane & 3;
#pragma unroll
    for (int mi = 0; mi < 2; ++mi) {
        const int r = row0 + wm * 32 + mi * 16 + g;
#pragma unroll
        for (int ni = 0; ni < 8; ++ni) {
            const int c = col0 + wn * 64 + ni * 8 + tg * 2;
            const float b0 = bias[c], b1 = bias[c + 1];
            float v00 = acc[mi][ni][0] + b0, v01 = acc[mi][ni][1] + b1;
            float v10 = acc[mi][ni][2] + b0, v11 = acc[mi][ni][3] + b1;
            if (epi == 1) {
                v00 = fmaxf(v00, 0.f); v00 *= v00;
                v01 = fmaxf(v01, 0.f); v01 *= v01;
                v10 = fmaxf(v10, 0.f); v10 *= v10;
                v11 = fmaxf(v11, 0.f); v11 *= v11;
            }
            *(float2*)(C + (size_t)r * N + c)       = make_float2(v00, v01);
            *(float2*)(C + (size_t)(r + 8) * N + c) = make_float2(v10, v11);
        }
    }
}

// ---------------------------------------------------------------------------
// Plain fp32 SGEMM (comb only).
// epi 0: +bias   epi 2: auxb[m][n] + auxg[m]*relu(x+bias)
// ---------------------------------------------------------------------------
__global__ void __launch_bounds__(256) sgemm_kernel(
    const float* __restrict__ A, const float* __restrict__ B,
    const float* __restrict__ bias, float* __restrict__ C,
    int M, int N, int K, int epi,
    const float* __restrict__ auxb, const float* __restrict__ auxg)
{
    __shared__ float As[16][132];
    __shared__ float Bs[16][132];
    const int tid = threadIdx.x;
    const int tx = tid & 15, ty = tid >> 4;
    const int row0 = blockIdx.y * 128, col0 = blockIdx.x * 128;

    float acc[8][8];
#pragma unroll
    for (int i = 0; i < 8; ++i)
#pragma unroll
        for (int j = 0; j < 8; ++j) acc[i][j] = 0.f;

    for (int k0 = 0; k0 < K; k0 += 16) {
#pragma unroll
        for (int i = 0; i < 2; ++i) {
            int v = tid + i * 256;
            int r = v >> 2;
            int kq = (v & 3) << 2;
            float4 av = *(const float4*)(A + (size_t)(row0 + r) * K + k0 + kq);
            As[kq + 0][r] = av.x; As[kq + 1][r] = av.y;
            As[kq + 2][r] = av.z; As[kq + 3][r] = av.w;
            float4 bv = *(const float4*)(B + (size_t)(col0 + r) * K + k0 + kq);
            Bs[kq + 0][r] = bv.x; Bs[kq + 1][r] = bv.y;
            Bs[kq + 2][r] = bv.z; Bs[kq + 3][r] = bv.w;
        }
        __syncthreads();
#pragma unroll
        for (int k = 0; k < 16; ++k) {
            float4 a0 = *(const float4*)&As[k][ty * 8];
            float4 a1 = *(const float4*)&As[k][ty * 8 + 4];
            float4 b0 = *(const float4*)&Bs[k][tx * 8];
            float4 b1 = *(const float4*)&Bs[k][tx * 8 + 4];
            float a[8] = {a0.x, a0.y, a0.z, a0.w, a1.x, a1.y, a1.z, a1.w};
            float b[8] = {b0.x, b0.y, b0.z, b0.w, b1.x, b1.y, b1.z, b1.w};
#pragma unroll
            for (int i = 0; i < 8; ++i)
#pragma unroll
                for (int j = 0; j < 8; ++j)
                    acc[i][j] = fmaf(a[i], b[j], acc[i][j]);
        }
        __syncthreads();
    }

#pragma unroll
    for (int i = 0; i < 8; ++i) {
        int m = row0 + ty * 8 + i;
#pragma unroll
        for (int j = 0; j < 8; j += 4) {
            int n = col0 + tx * 8 + j;
            float o[4];
#pragma unroll
            for (int u = 0; u < 4; ++u) {
                float x = acc[i][j + u] + bias[n + u];
                if (epi == 2)
                    x = auxb[(size_t)m * N + n + u] + auxg[m] * fmaxf(x, 0.f);
                o[u] = x;
            }
            *(float4*)(C + (size_t)m * N + n) = make_float4(o[0], o[1], o[2], o[3]);
        }
    }
}

// ---------------------------------------------------------------------------
// GRU: persistent kernel (unchanged — R13/R15 proven version)
// ---------------------------------------------------------------------------
#define GRU_CTAS    128
#define GRU_THREADS 256
#define GRU_SMEM    ((24 * HDIM + BATCH * HDIM) * 4)

__device__ __forceinline__ float warp_sum(float v) {
#pragma unroll
    for (int o = 16; o; o >>= 1) v += __shfl_xor_sync(0xffffffffu, v, o);
    return v;
}

__global__ void __launch_bounds__(GRU_THREADS, 1) gru_kernel(
    const float* __restrict__ xp, const float* __restrict__ w_hh,
    const float* __restrict__ b_hh)
{
    extern __shared__ float sm[];
    float* wsm = sm;                       // [24][HDIM], row = gate*8 + jl
    float* hsm = sm + 24 * HDIM;           // [BATCH][HDIM]
    const int tid = threadIdx.x;
    const int w = tid >> 5, lane = tid & 31;
    const int j0 = blockIdx.x * 8;

    for (int v = tid; v < 24 * (HDIM / 4); v += GRU_THREADS) {
        int rowl = v / (HDIM / 4);
        int c4 = v % (HDIM / 4);
        int g = rowl >> 3, jl = rowl & 7;
        ((float4*)wsm)[(size_t)rowl * (HDIM / 4) + c4] =
            ((const float4*)w_hh)[(size_t)(g * HDIM + j0 + jl) * (HDIM / 4) + c4];
    }
    const int j = j0 + w;
    const float bhr = b_hh[j];
    const float bhz = b_hh[HDIM + j];
    const float bhn = b_hh[2 * HDIM + j];
    __syncthreads();

    float xv0 = 0.f, xv1 = 0.f, xv2 = 0.f;
    if (lane < 2) {
        const float* xpt = xp + ((size_t)lane * S_LEN) * (3 * HDIM);
        xv0 = xpt[j]; xv1 = xpt[HDIM + j]; xv2 = xpt[2 * HDIM + j];
    }

    for (int s = 0; s < S_LEN; ++s) {
        const float* h_in = g_h + (s & 1) * (BATCH * HDIM);
        float* h_out      = g_h + ((s + 1) & 1) * (BATCH * HDIM);

        for (int v = tid; v < (BATCH * HDIM) / 4; v += GRU_THREADS)
            ((float4*)hsm)[v] = __ldcg(((const float4*)h_in) + v);
        __syncthreads();

        float xn0 = 0.f, xn1 = 0.f, xn2 = 0.f;
        if (lane < 2 && s + 1 < S_LEN) {
            const float* xpt = xp + ((size_t)lane * S_LEN + s + 1) * (3 * HDIM);
            xn0 = __ldg(xpt + j);
            xn1 = __ldg(xpt + HDIM + j);
            xn2 = __ldg(xpt + 2 * HDIM + j);
        }

        float4 H0[8], H1[8];
#pragma unroll
        for (int c = 0; c < 8; ++c) {
            H0[c] = ((const float4*)hsm)[lane + 32 * c];
            H1[c] = ((const float4*)(hsm + HDIM))[lane + 32 * c];
        }
        float acc[3][2];
#pragma unroll
        for (int g = 0; g < 3; ++g) {
            const float4* wp = (const float4*)(wsm + (size_t)(g * 8 + w) * HDIM);
            float s0a = 0.f, s0b = 0.f, s1a = 0.f, s1b = 0.f;
#pragma unroll
            for (int c = 0; c < 8; ++c) {
                float4 wv = wp[lane + 32 * c];
                s0a = fmaf(wv.x, H0[c].x, s0a); s0b = fmaf(wv.y, H0[c].y, s0b);
                s0a = fmaf(wv.z, H0[c].z, s0a); s0b = fmaf(wv.w, H0[c].w, s0b);
                s1a = fmaf(wv.x, H1[c].x, s1a); s1b = fmaf(wv.y, H1[c].y, s1b);
                s1a = fmaf(wv.z, H1[c].z, s1a); s1b = fmaf(wv.w, H1[c].w, s1b);
            }
            acc[g][0] = warp_sum(s0a + s0b);   // result in ALL lanes
            acc[g][1] = warp_sum(s1a + s1b);
        }

        if (lane < 2) {
            const int b = lane;
            size_t t = (size_t)b * S_LEN + s;
            float r = 1.f / (1.f + __expf(-(xv0 + acc[0][b] + bhr)));
            float z = 1.f / (1.f + __expf(-(xv1 + acc[1][b] + bhz)));
            float n = tanhf(xv2 + r * (acc[2][b] + bhn));
            float hp = hsm[b * HDIM + j];
            float hn2 = (1.f - z) * n + z * hp;
            g_states[t * HDIM + j] = hn2;
            __stcg(h_out + b * HDIM + j, hn2);
        }
        xv0 = xn0; xv1 = xn1; xv2 = xn2;
        __syncthreads();

        // --- grid barrier: monotonic counter, direct poll ---
        if (tid == 0) {
            __threadfence();
            atomicAdd(&g_bar_cnt, 1u);
            const unsigned target = (unsigned)GRU_CTAS * (unsigned)(s + 1);
            while (*((volatile unsigned*)&g_bar_cnt) < target) { }
            __threadfence();
        }
        __syncthreads();
    }
}

// ---------------------------------------------------------------------------
// gate[t] = sigmoid(states[t] . Wg + bg)
// ---------------------------------------------------------------------------
__global__ void gate_kernel(const float* __restrict__ Wg,
                            const float* __restrict__ bg) {
    int t = blockIdx.x;
    int tid = threadIdx.x;
    const float4* sp = (const float4*)(g_states + (size_t)t * HDIM);
    const float4* wp = (const float4*)Wg;
    float s = 0.f;
    for (int c = tid; c < HDIM / 4; c += 128) {
        float4 a = sp[c], ww = wp[c];
        s += a.x * ww.x + a.y * ww.y + a.z * ww.z + a.w * ww.w;
    }
    __shared__ float red[128];
    red[tid] = s; __syncthreads();
    for (int k = 64; k; k >>= 1) {
        if (tid < k) red[tid] += red[tid + k];
        __syncthreads();
    }
    if (tid == 0) g_gate[t] = 1.f / (1.f + expf(-(red[0] + bg[0])));
}

// ---------------------------------------------------------------------------
// Softmax + scatter-add: reads the precomputed score matrix (g_sc) instead
// of recomputing q.k dots. Strictly-causal prefix softmax; row q==0 skipped.
// ---------------------------------------------------------------------------
__global__ void __launch_bounds__(256) attn_scatter_kernel(
    const int* __restrict__ ids, const float* __restrict__ mscale,
    const float* __restrict__ sc_mat, float* __restrict__ out)
{
    int bq = blockIdx.x;
    int b = bq >> 10, qpos = bq & 1023;
    if (qpos == 0) return;
    int tid = threadIdx.x;

    const float* srow = sc_mat + ((size_t)b * S_LEN + qpos) * S_LEN;
    __shared__ float red[256];

    const int nk = qpos;
    float sc[4];
    int cnt = 0;
    float mx = -1e30f;
    for (int kp = tid; kp < nk; kp += 256) {
        float d = srow[kp] * 0.0625f;      // 1/sqrt(256)
        sc[cnt++] = d;
        mx = fmaxf(mx, d);
    }
    red[tid] = mx; __syncthreads();
    for (int k = 128; k; k >>= 1) {
        if (tid < k) red[tid] = fmaxf(red[tid], red[tid + k]);
        __syncthreads();
    }
    mx = red[0]; __syncthreads();

    float sum = 0.f;
    for (int i = 0; i < cnt; ++i) { sc[i] = expf(sc[i] - mx); sum += sc[i]; }
    red[tid] = sum; __syncthreads();
    for (int k = 128; k; k >>= 1) {
        if (tid < k) red[tid] += red[tid + k];
        __syncthreads();
    }
    sum = red[0];

    float coef = g_gate[bq] * mscale[0] / sum;
    int i2 = 0;
    for (int kp = tid; kp < nk; kp += 256) {
        int vid = ids[b * S_LEN + kp];
        atomicAdd(out + (size_t)bq * VDIM + vid, sc[i2++] * coef);
    }
}

// ---------------------------------------------------------------------------
// Host launcher
// ---------------------------------------------------------------------------
extern "C" void kernel_launch(void* const* d_in, const int* in_sizes, int n_in,
                              void* d_out, int out_size) {
    (void)in_sizes; (void)n_in; (void)out_size;
    const int*   ids    = (const int*)d_in[0];
    const float* embW   = (const float*)d_in[1];
    const float* w_ih   = (const float*)d_in[2];
    const float* w_hh   = (const float*)d_in[3];
    const float* b_ih   = (const float*)d_in[4];
    const float* b_hh   = (const float*)d_in[5];
    const float* Wq     = (const float*)d_in[6];
    const float* bq     = (const float*)d_in[7];
    const float* Wk     = (const float*)d_in[8];
    const float* bk     = (const float*)d_in[9];
    const float* Wg     = (const float*)d_in[10];
    const float* bg     = (const float*)d_in[11];
    const float* W1     = (const float*)d_in[12];
    const float* b1     = (const float*)d_in[13];
    const float* W2     = (const float*)d_in[14];
    const float* b2     = (const float*)d_in[15];
    const float* Wr     = (const float*)d_in[16];
    const float* br     = (const float*)d_in[17];
    const float* mscale = (const float*)d_in[18];
    const float* obias  = (const float*)d_in[19];
    float* out = (float*)d_out;

    float *p_xp, *p_states, *p_hf, *p_base, *p_comb, *p_gate, *p_q, *p_k,
          *p_sc, *p_zero;
    cudaGetSymbolAddress((void**)&p_xp,     g_xp);
    cudaGetSymbolAddress((void**)&p_states, g_states);
    cudaGetSymbolAddress((void**)&p_hf,     g_hf);
    cudaGetSymbolAddress((void**)&p_base,   g_base);
    cudaGetSymbolAddress((void**)&p_comb,   g_comb);
    cudaGetSymbolAddress((void**)&p_gate,   g_gate);
    cudaGetSymbolAddress((void**)&p_q,      g_q);
    cudaGetSymbolAddress((void**)&p_k,      g_k);
    cudaGetSymbolAddress((void**)&p_sc,     g_sc);
    cudaGetSymbolAddress((void**)&p_zero,   g_zero);

    __nv_bfloat16 *q_embW_h, *q_embW_l, *q_emb_h, *q_emb_l, *q_wih_h, *q_wih_l,
                  *q_st_h, *q_st_l, *q_W1_h, *q_W1_l, *q_hf_h, *q_hf_l,
                  *q_W2_h, *q_W2_l, *q_comb_h, *q_comb_l,
                  *q_Wq_h, *q_Wq_l, *q_Wk_h, *q_Wk_l,
                  *q_qs_h, *q_qs_l, *q_ks_h, *q_ks_l;
    cudaGetSymbolAddress((void**)&q_embW_h, s_embW_h);
    cudaGetSymbolAddress((void**)&q_embW_l, s_embW_l);
    cudaGetSymbolAddress((void**)&q_emb_h,  s_emb_h);
    cudaGetSymbolAddress((void**)&q_emb_l,  s_emb_l);
    cudaGetSymbolAddress((void**)&q_wih_h,  s_wih_h);
    cudaGetSymbolAddress((void**)&q_wih_l,  s_wih_l);
    cudaGetSymbolAddress((void**)&q_st_h,   s_st_h);
    cudaGetSymbolAddress((void**)&q_st_l,   s_st_l);
    cudaGetSymbolAddress((void**)&q_W1_h,   s_W1_h);
    cudaGetSymbolAddress((void**)&q_W1_l,   s_W1_l);
    cudaGetSymbolAddress((void**)&q_hf_h,   s_hf_h);
    cudaGetSymbolAddress((void**)&q_hf_l,   s_hf_l);
    cudaGetSymbolAddress((void**)&q_W2_h,   s_W2_h);
    cudaGetSymbolAddress((void**)&q_W2_l,   s_W2_l);
    cudaGetSymbolAddress((void**)&q_comb_h, s_comb_h);
    cudaGetSymbolAddress((void**)&q_comb_l, s_comb_l);
    cudaGetSymbolAddress((void**)&q_Wq_h,   s_Wq_h);
    cudaGetSymbolAddress((void**)&q_Wq_l,   s_Wq_l);
    cudaGetSymbolAddress((void**)&q_Wk_h,   s_Wk_h);
    cudaGetSymbolAddress((void**)&q_Wk_l,   s_Wk_l);
    cudaGetSymbolAddress((void**)&q_qs_h,   s_qs_h);
    cudaGetSymbolAddress((void**)&q_qs_l,   s_qs_l);
    cudaGetSymbolAddress((void**)&q_ks_h,   s_ks_h);
    cudaGetSymbolAddress((void**)&q_ks_l,   s_ks_l);

    cudaFuncSetAttribute(gru_kernel,
                         cudaFuncAttributeMaxDynamicSharedMemorySize, GRU_SMEM);
    cudaFuncSetAttribute(hmma_kernel,
                         cudaFuncAttributeMaxDynamicSharedMemorySize, HMMA_SMEM);

    auto split = [&](const float* src, __nv_bfloat16* h, __nv_bfloat16* l, int n) {
        int n4 = n / 4;
        split_kernel<<<(n4 + 255) / 256, 256>>>(src, h, l, n4);
    };

    // Launch order arranged so gru_kernel is the 6th launch (ncu -s 5 -c 1
    // profiles it next round). Dependencies all preserved.
    init_kernel<<<16, 256>>>();                            // 1
    embed_split_kernel<<<NTOK, 128>>>(ids, embW);          // 2
    split(w_ih, q_wih_h, q_wih_l, 3 * HDIM * EDIM);        // 3

    // xp = emb @ w_ih^T + b_ih   [2048, 3072]
    hmma_kernel<<<dim3(NTOK / 128, 3 * HDIM / 128), 256, HMMA_SMEM>>>(   // 4
        q_emb_h, q_emb_l, q_wih_h, q_wih_l, b_ih, p_xp, NTOK, 3 * HDIM, EDIM, 0);

    split(embW, q_embW_h, q_embW_l, VDIM * EDIM);          // 5 (indep of gru)

    // Recurrent scan -> g_states                          // 6 <- ncu target
    gru_kernel<<<GRU_CTAS, GRU_THREADS, GRU_SMEM>>>(p_xp, w_hh, b_hh);

    // Remaining weight splits (only needed after gru anyway)
    split(W1, q_W1_h, q_W1_l, 4 * EDIM * HDIM);
    split(W2, q_W2_h, q_W2_l, EDIM * 4 * EDIM);
    split(Wq, q_Wq_h, q_Wq_l, MDIM * HDIM);
    split(Wk, q_Wk_h, q_Wk_l, MDIM * HDIM);

    gate_kernel<<<NTOK, 128>>>(Wg, bg);
    split(p_states, q_st_h, q_st_l, NTOK * HDIM);

    // hf = relu(states @ W1^T + b1)^2   [2048, 2048]
    hmma_kernel<<<dim3(NTOK / 128, 4 * EDIM / 128), 256, HMMA_SMEM>>>(
        q_st_h, q_st_l, q_W1_h, q_W1_l, b1, p_hf, NTOK, 4 * EDIM, HDIM, 1);
    split(p_hf, q_hf_h, q_hf_l, NTOK * 4 * EDIM);

    // base = hf @ W2^T + b2             [2048, 512]
    hmma_kernel<<<dim3(NTOK / 128, EDIM / 128), 256, HMMA_SMEM>>>(
        q_hf_h, q_hf_l, q_W2_h, q_W2_l, b2, p_base, NTOK, EDIM, 4 * EDIM, 0);

    // comb = base + gate * relu(base @ Wr^T + br)   [2048, 512]
    sgemm_kernel<<<dim3(EDIM / 128, NTOK / 128), 256>>>(
        p_base, Wr, br, p_comb, NTOK, EDIM, EDIM, 2, p_base, p_gate);

    // q / k projections [2048, 256] on hmma
    hmma_kernel<<<dim3(NTOK / 128, MDIM / 128), 256, HMMA_SMEM>>>(
        q_st_h, q_st_l, q_Wq_h, q_Wq_l, bq, p_q, NTOK, MDIM, HDIM, 0);
    hmma_kernel<<<dim3(NTOK / 128, MDIM / 128), 256, HMMA_SMEM>>>(
        q_st_h, q_st_l, q_Wk_h, q_Wk_l, bk, p_k, NTOK, MDIM, HDIM, 0);

    // scores[b] = q[b] @ k[b]^T  [1024, 1024, K=256] per batch, via hmma
    split(p_q, q_qs_h, q_qs_l, NTOK * MDIM);
    split(p_k, q_ks_h, q_ks_l, NTOK * MDIM);
    for (int b = 0; b < BATCH; ++b) {
        size_t ofs = (size_t)b * S_LEN * MDIM;
        hmma_kernel<<<dim3(S_LEN / 128, S_LEN / 128), 256, HMMA_SMEM>>>(
            q_qs_h + ofs, q_qs_l + ofs, q_ks_h + ofs, q_ks_l + ofs,
            p_zero, p_sc + (size_t)b * S_LEN * S_LEN, S_LEN, S_LEN, MDIM, 0);
    }

    split(p_comb, q_comb_h, q_comb_l, NTOK * EDIM);

    // logits = comb @ emb_W^T + output_bias   [2048, 32000] -> d_out
    hmma_kernel<<<dim3(NTOK / 128, VDIM / 128), 256, HMMA_SMEM>>>(
        q_comb_h, q_comb_l, q_embW_h, q_embW_l, obias, out, NTOK, VDIM, EDIM, 0);

    // softmax + scatter-add of gated attention into logits
    attn_scatter_kernel<<<NTOK, 256>>>(ids, mscale, p_sc, out);
}